// round 8
// baseline (speedup 1.0000x reference)
#include <cuda_runtime.h>
#include <cuda_bf16.h>
#include <math.h>
#include <stdint.h>

// Problem constants (fixed by the reference setup_inputs)
#define E_  3
#define B_  4096
#define D_  1024
#define M_  5
#define N_  256

#define NB_DOT 512          // blocks for the big feature*gt reduction
#define NB_SIM 96           // 3 e * 32 blocks, each block = 8 warps, 1 n per warp
#define TPB 256

// per block: 6144 contiguous float4 per array (96KB each)
#define CHUNK4 (3145728 / NB_DOT)   // 6144
#define PIPE 4
#define STG4 256                    // float4 per stage per array = 4KB
#define NSTG (CHUNK4 / STG4)        // 24
#define STG_BYTES (STG4 * 16)       // 4096
#define TX_BYTES (2 * STG_BYTES)    // 8192 (f + g per stage)

// Scratch (allocation-free rule: __device__ globals)
__device__ float g_dot_partial[NB_DOT];
__device__ float g_dotmn[E_][M_][N_];   // raw dot(gt_local[m], feature_local[n])
__device__ float g_fnorm2[E_][N_];      // ||f_n||^2
__device__ float g_ot[E_];

static __device__ __forceinline__ float dot4(float4 a, float4 b) {
    return a.x * b.x + a.y * b.y + a.z * b.z + a.w * b.w;
}

static __device__ __forceinline__ uint32_t smem_u32(const void* p) {
    return (uint32_t)__cvta_generic_to_shared(p);
}

static __device__ __forceinline__ void mbar_init(uint32_t mbar, uint32_t count) {
    asm volatile("mbarrier.init.shared.b64 [%0], %1;" :: "r"(mbar), "r"(count) : "memory");
}
static __device__ __forceinline__ void mbar_expect_tx(uint32_t mbar, uint32_t bytes) {
    asm volatile("mbarrier.arrive.expect_tx.shared.b64 _, [%0], %1;"
                 :: "r"(mbar), "r"(bytes) : "memory");
}
static __device__ __forceinline__ void mbar_arrive(uint32_t mbar) {
    asm volatile("mbarrier.arrive.shared.b64 _, [%0];" :: "r"(mbar) : "memory");
}
static __device__ __forceinline__ void mbar_wait(uint32_t mbar, uint32_t phase) {
    asm volatile(
        "{\n\t"
        ".reg .pred P;\n\t"
        "WAIT_%=:\n\t"
        "mbarrier.try_wait.parity.shared.b64 P, [%0], %1;\n\t"
        "@P bra.uni DONE_%=;\n\t"
        "bra.uni WAIT_%=;\n\t"
        "DONE_%=:\n\t"
        "}"
        :: "r"(mbar), "r"(phase) : "memory");
}
static __device__ __forceinline__ void bulk_g2s(uint32_t dst, const void* src,
                                                uint32_t bytes, uint32_t mbar) {
    asm volatile(
        "cp.async.bulk.shared::cluster.global.mbarrier::complete_tx::bytes "
        "[%0], [%1], %2, [%3];"
        :: "r"(dst), "l"(src), "r"(bytes), "r"(mbar) : "memory");
}

// ---------------------------------------------------------------------------
// Kernel 1: (a) blocks [0, NB_DOT): feature*gt dot streamed via TMA bulk
//               copies (24 stages x 4KB/array, 4-slot mbarrier pipeline);
//           (b) blocks [NB_DOT, NB_DOT+NB_SIM): sim raw dots + f-row norms.
// ---------------------------------------------------------------------------
__global__ void __launch_bounds__(TPB, 4) k_main(
    const float* __restrict__ feature,
    const float* __restrict__ gt,
    const float* __restrict__ gt_local,
    const float* __restrict__ feature_local)
{
    __shared__ float4 s_f[PIPE][STG4];
    __shared__ float4 s_g[PIPE][STG4];
    __shared__ __align__(8) unsigned long long s_full[PIPE];
    __shared__ __align__(8) unsigned long long s_empty[PIPE];

    const int b = blockIdx.x;
    const int tid = threadIdx.x;

    if (b < NB_DOT) {
        // ---- big streaming reduction via TMA bulk pipeline ----
        const float4* fa = reinterpret_cast<const float4*>(feature) + b * CHUNK4;
        const float4* ga = reinterpret_cast<const float4*>(gt) + b * CHUNK4;

        uint32_t full_a[PIPE], empty_a[PIPE], dst_f[PIPE], dst_g[PIPE];
        #pragma unroll
        for (int s = 0; s < PIPE; ++s) {
            full_a[s]  = smem_u32(&s_full[s]);
            empty_a[s] = smem_u32(&s_empty[s]);
            dst_f[s]   = smem_u32(&s_f[s][0]);
            dst_g[s]   = smem_u32(&s_g[s][0]);
        }

        if (tid == 0) {
            #pragma unroll
            for (int s = 0; s < PIPE; ++s) {
                mbar_init(full_a[s], 1);        // 1 arrive (expect_tx) + tx bytes
                mbar_init(empty_a[s], TPB);     // all consumers arrive
            }
            asm volatile("fence.proxy.async.shared::cta;" ::: "memory");
        }
        __syncthreads();

        // prologue: fill all PIPE slots
        if (tid == 0) {
            #pragma unroll
            for (int s = 0; s < PIPE; ++s) {
                mbar_expect_tx(full_a[s], TX_BYTES);
                bulk_g2s(dst_f[s], fa + s * STG4, STG_BYTES, full_a[s]);
                bulk_g2s(dst_g[s], ga + s * STG4, STG_BYTES, full_a[s]);
            }
        }

        float acc0 = 0.f, acc1 = 0.f, acc2 = 0.f, acc3 = 0.f;
        #pragma unroll 1
        for (int k = 0; k < NSTG; ++k) {
            const int slot = k & (PIPE - 1);
            const uint32_t fph = (uint32_t)((k >> 2) & 1);
            mbar_wait(full_a[slot], fph);

            float4 x = s_f[slot][tid];
            float4 y = s_g[slot][tid];
            float d = dot4(x, y);
            if (slot == 0) acc0 += d;
            else if (slot == 1) acc1 += d;
            else if (slot == 2) acc2 += d;
            else acc3 += d;

            mbar_arrive(empty_a[slot]);

            if (tid == 0 && k + PIPE < NSTG) {
                const int j = k + PIPE;               // same slot
                mbar_wait(empty_a[slot], fph);        // all 256 consumed stage k
                mbar_expect_tx(full_a[slot], TX_BYTES);
                bulk_g2s(dst_f[slot], fa + j * STG4, STG_BYTES, full_a[slot]);
                bulk_g2s(dst_g[slot], ga + j * STG4, STG_BYTES, full_a[slot]);
            }
        }
        float acc = (acc0 + acc1) + (acc2 + acc3);

        // warp reduce + single-sync block reduce
        #pragma unroll
        for (int off = 16; off > 0; off >>= 1)
            acc += __shfl_down_sync(0xFFFFFFFFu, acc, off);

        __shared__ float sh[8];
        const int w = tid >> 5;
        const int lane = tid & 31;
        if (lane == 0) sh[w] = acc;
        __syncthreads();
        if (w == 0) {
            float s = (lane < 8) ? sh[lane] : 0.0f;
            #pragma unroll
            for (int off = 4; off > 0; off >>= 1)
                s += __shfl_down_sync(0xFFFFFFFFu, s, off);
            if (lane == 0) g_dot_partial[b] = s;
        }
    } else {
        // ---- sim raw dots + feature_local row norms (unchanged) ----
        const int sb = b - NB_DOT;          // 0..95
        const int e  = sb / 32;             // 3 extractors
        const int w  = tid >> 5;            // warp id 0..7
        const int lane = tid & 31;
        const int n  = (sb % 32) * 8 + w;   // 0..255

        const float* __restrict__ f = feature_local + ((size_t)e * N_ + n) * D_;
        const float* __restrict__ g = gt_local + (size_t)e * M_ * D_;

        float acc[M_] = {0.f, 0.f, 0.f, 0.f, 0.f};
        float fn = 0.f;
        for (int d = lane; d < D_; d += 32) {
            float fv = f[d];
            fn += fv * fv;
            #pragma unroll
            for (int m = 0; m < M_; m++)
                acc[m] += g[m * D_ + d] * fv;
        }
        #pragma unroll
        for (int off = 16; off > 0; off >>= 1) {
            fn += __shfl_down_sync(0xFFFFFFFFu, fn, off);
            #pragma unroll
            for (int m = 0; m < M_; m++)
                acc[m] += __shfl_down_sync(0xFFFFFFFFu, acc[m], off);
        }
        if (lane == 0) {
            #pragma unroll
            for (int m = 0; m < M_; m++)
                g_dotmn[e][m][n] = acc[m];
            g_fnorm2[e][n] = fn;
        }
    }
}

// ---------------------------------------------------------------------------
// Kernel 2: per-extractor Sinkhorn (one 256-thread block per e).
// (Proven-fast R2 version.)
// ---------------------------------------------------------------------------
__global__ void __launch_bounds__(TPB) k_sinkhorn(
    const float* __restrict__ gt_local)
{
    const int e = blockIdx.x;
    const int tid = threadIdx.x;         // == n
    const int w = tid >> 5;
    const int lane = tid & 31;

    __shared__ float sh_gn[M_];          // ||g_m||
    __shared__ float sred[8 * M_];       // per-warp partials for K@c
    __shared__ float sh_r[M_];           // row scaling vector
    __shared__ float sh_scalar[8];       // final reduction

    // gt_local row norms: warps 0..4, one row each
    if (w < M_) {
        const float* g = gt_local + ((size_t)e * M_ + w) * D_;
        float s = 0.f;
        for (int d = lane; d < D_; d += 32) {
            float v = g[d];
            s += v * v;
        }
        #pragma unroll
        for (int off = 16; off > 0; off >>= 1)
            s += __shfl_down_sync(0xFFFFFFFFu, s, off);
        if (lane == 0) sh_gn[w] = sqrtf(s);
    }
    __syncthreads();

    // Build sim[m][n] and K[m][n] in registers
    const float fn = fmaxf(sqrtf(g_fnorm2[e][tid]), 1e-12f);
    float simv[M_], Kv[M_];
    #pragma unroll
    for (int m = 0; m < M_; m++) {
        const float gn = fmaxf(sh_gn[m], 1e-12f);
        simv[m] = g_dotmn[e][m][tid] / (gn * fn);
        Kv[m] = __expf((simv[m] - 1.0f) * 10.0f);   // exp(-(1-sim)/0.1)
    }

    // Sinkhorn loop (mirrors the reference exactly)
    const float u = 1.0f / (float)M_;
    const float vv = 1.0f / (float)N_;
    float c = 1.0f;
    float r[M_] = {1.f, 1.f, 1.f, 1.f, 1.f};
    float err = 1e9f;

    for (int it = 0; it < 100 && err >= 0.01f; ++it) {
        // Kc[m] = sum_n K[m][n] * c[n]
        float p[M_];
        #pragma unroll
        for (int m = 0; m < M_; m++) p[m] = Kv[m] * c;
        #pragma unroll
        for (int off = 16; off > 0; off >>= 1) {
            #pragma unroll
            for (int m = 0; m < M_; m++)
                p[m] += __shfl_down_sync(0xFFFFFFFFu, p[m], off);
        }
        if (lane == 0) {
            #pragma unroll
            for (int m = 0; m < M_; m++) sred[w * M_ + m] = p[m];
        }
        __syncthreads();
        if (tid < M_) {
            float s = 0.f;
            #pragma unroll
            for (int ww = 0; ww < 8; ww++) s += sred[ww * M_ + tid];
            sh_r[tid] = u / s;           // r = u / (K @ c)
        }
        __syncthreads();
        // all threads: identical update of r, err, c  (uniform branch)
        float errs = 0.f;
        #pragma unroll
        for (int m = 0; m < M_; m++) {
            float rn = sh_r[m];
            errs += fabsf(rn - r[m]);
            r[m] = rn;
        }
        err = errs * (1.0f / (float)M_);
        float ktr = 0.f;
        #pragma unroll
        for (int m = 0; m < M_; m++) ktr += Kv[m] * r[m];
        c = vv / ktr;                    // c = v / (K^T @ r)
    }

    // ot = sum_{m,n} r[m]*c[n]*K[m][n]*sim[m][n]
    float t = 0.f;
    #pragma unroll
    for (int m = 0; m < M_; m++) t += r[m] * Kv[m] * simv[m];
    t *= c;
    #pragma unroll
    for (int off = 16; off > 0; off >>= 1)
        t += __shfl_down_sync(0xFFFFFFFFu, t, off);
    if (lane == 0) sh_scalar[w] = t;
    __syncthreads();
    if (tid == 0) {
        float s = 0.f;
        #pragma unroll
        for (int ww = 0; ww < 8; ww++) s += sh_scalar[ww];
        g_ot[e] = s;
    }
}

// ---------------------------------------------------------------------------
// Kernel 3: finalize — deterministic sum of partials + scalar combine
// ---------------------------------------------------------------------------
__global__ void __launch_bounds__(TPB) k_final(float* __restrict__ out)
{
    const int tid = threadIdx.x;
    __shared__ float sh[TPB];
    float s = 0.f;
    for (int i = tid; i < NB_DOT; i += TPB) s += g_dot_partial[i];
    sh[tid] = s;
    __syncthreads();
    #pragma unroll
    for (int st = TPB / 2; st > 0; st >>= 1) {
        if (tid < st) sh[tid] += sh[tid + st];
        __syncthreads();
    }
    if (tid == 0) {
        float loss_global = sh[0] / (float)(E_ * B_);
        float loss_local = (g_ot[0] + g_ot[1] + g_ot[2]) * 2.0f / (float)E_;
        out[0] = loss_global + 0.1f * loss_local;
    }
}

// ---------------------------------------------------------------------------
extern "C" void kernel_launch(void* const* d_in, const int* in_sizes, int n_in,
                              void* d_out, int out_size)
{
    const float* feature        = (const float*)d_in[0];
    const float* gt             = (const float*)d_in[1];
    const float* gt_local       = (const float*)d_in[2];
    const float* feature_local  = (const float*)d_in[3];
    float* out = (float*)d_out;

    k_main<<<NB_DOT + NB_SIM, TPB>>>(feature, gt, gt_local, feature_local);
    k_sinkhorn<<<E_, TPB>>>(gt_local);
    k_final<<<1, TPB>>>(out);
}

// round 9
// speedup vs baseline: 1.3542x; 1.3542x over previous
#include <cuda_runtime.h>
#include <cuda_bf16.h>
#include <math.h>

// Problem constants (fixed by the reference setup_inputs)
#define E_  3
#define B_  4096
#define D_  1024
#define M_  5
#define N_  256

#define NB_ALL 608          // all blocks stream dot work; last 96 also do sim
#define NB_SIMBASE 512      // blocks [512,608) run the sim stage first
#define TPB 256

// Ragged dot partition (float4 pairs per thread):
//   blocks   0..31  : 6 iters x 4 = 24 pairs   (chunk 6144 float4)
//   blocks  32..511 : 5 iters x 4 = 20 pairs   (chunk 5120 float4)
//   blocks 512..607 : 5 iters x 4 = 20 pairs   (chunk 5120 float4)
// total = 256*(32*24 + 576*20) = 3,145,728 float4 pairs  (exact)

// Scratch (allocation-free rule: __device__ globals)
__device__ float g_dot_partial[NB_ALL];
__device__ float g_dotmn[E_][M_][N_];   // raw dot(gt_local[m], feature_local[n])
__device__ float g_fnorm2[E_][N_];      // ||f_n||^2
__device__ float g_ot[E_];

static __device__ __forceinline__ float dot4(float4 a, float4 b) {
    return a.x * b.x + a.y * b.y + a.z * b.z + a.w * b.w;
}

// ---------------------------------------------------------------------------
// Kernel 1: every block streams a contiguous slice of feature*gt with
// 8 front-batched LDG.128 per iteration (empirically optimal). Blocks
// [512,608) first compute the sim raw dots + feature_local row norms.
// ---------------------------------------------------------------------------
__global__ void __launch_bounds__(TPB, 4) k_main(
    const float* __restrict__ feature,
    const float* __restrict__ gt,
    const float* __restrict__ gt_local,
    const float* __restrict__ feature_local)
{
    const int b = blockIdx.x;
    const int tid = threadIdx.x;
    const int w = tid >> 5;
    const int lane = tid & 31;

    if (b >= NB_SIMBASE) {
        // ---- sim raw dots + feature_local row norms (runs first) ----
        const int sb = b - NB_SIMBASE;      // 0..95
        const int e  = sb / 32;             // 3 extractors
        const int n  = (sb % 32) * 8 + w;   // 0..255

        const float* __restrict__ f = feature_local + ((size_t)e * N_ + n) * D_;
        const float* __restrict__ g = gt_local + (size_t)e * M_ * D_;

        float acc[M_] = {0.f, 0.f, 0.f, 0.f, 0.f};
        float fn = 0.f;
        for (int d = lane; d < D_; d += 32) {
            float fv = f[d];
            fn += fv * fv;
            #pragma unroll
            for (int m = 0; m < M_; m++)
                acc[m] += g[m * D_ + d] * fv;
        }
        #pragma unroll
        for (int off = 16; off > 0; off >>= 1) {
            fn += __shfl_down_sync(0xFFFFFFFFu, fn, off);
            #pragma unroll
            for (int m = 0; m < M_; m++)
                acc[m] += __shfl_down_sync(0xFFFFFFFFu, acc[m], off);
        }
        if (lane == 0) {
            #pragma unroll
            for (int m = 0; m < M_; m++)
                g_dotmn[e][m][n] = acc[m];
            g_fnorm2[e][n] = fn;
        }
    }

    // ---- big streaming reduction: sum(feature * gt), ragged partition ----
    int iters, start4;
    if (b < 32) {
        iters = 6;
        start4 = b * (6 * 4 * TPB);                               // b*6144
    } else if (b < NB_SIMBASE) {
        iters = 5;
        start4 = 32 * 6144 + (b - 32) * (5 * 4 * TPB);            // +*5120
    } else {
        iters = 5;
        start4 = 32 * 6144 + 480 * 5120 + (b - NB_SIMBASE) * 5120;
    }

    const float4* fa = reinterpret_cast<const float4*>(feature);
    const float4* ga = reinterpret_cast<const float4*>(gt);
    int i = start4 + tid;
    float acc0 = 0.f, acc1 = 0.f, acc2 = 0.f, acc3 = 0.f;
    #pragma unroll 1
    for (int k = 0; k < iters; ++k) {
        // 8 independent 16B loads front-batched (read-once: evict-first)
        float4 x0 = __ldcs(&fa[i]);
        float4 x1 = __ldcs(&fa[i + TPB]);
        float4 x2 = __ldcs(&fa[i + 2 * TPB]);
        float4 x3 = __ldcs(&fa[i + 3 * TPB]);
        float4 y0 = __ldcs(&ga[i]);
        float4 y1 = __ldcs(&ga[i + TPB]);
        float4 y2 = __ldcs(&ga[i + 2 * TPB]);
        float4 y3 = __ldcs(&ga[i + 3 * TPB]);
        acc0 += dot4(x0, y0);
        acc1 += dot4(x1, y1);
        acc2 += dot4(x2, y2);
        acc3 += dot4(x3, y3);
        i += 4 * TPB;
    }
    float acc = (acc0 + acc1) + (acc2 + acc3);

    // warp reduce + single-sync block reduce
    #pragma unroll
    for (int off = 16; off > 0; off >>= 1)
        acc += __shfl_down_sync(0xFFFFFFFFu, acc, off);

    __shared__ float sh[8];
    if (lane == 0) sh[w] = acc;
    __syncthreads();
    if (w == 0) {
        float s = (lane < 8) ? sh[lane] : 0.0f;
        #pragma unroll
        for (int off = 4; off > 0; off >>= 1)
            s += __shfl_down_sync(0xFFFFFFFFu, s, off);
        if (lane == 0) g_dot_partial[b] = s;
    }
}

// ---------------------------------------------------------------------------
// Kernel 2: per-extractor Sinkhorn (one 256-thread block per e).
// Thread t owns column n = t of the 5 x 256 sim/K matrices (in registers).
// (Proven-fast R2 version.)
// ---------------------------------------------------------------------------
__global__ void __launch_bounds__(TPB) k_sinkhorn(
    const float* __restrict__ gt_local)
{
    const int e = blockIdx.x;
    const int tid = threadIdx.x;         // == n
    const int w = tid >> 5;
    const int lane = tid & 31;

    __shared__ float sh_gn[M_];          // ||g_m||
    __shared__ float sred[8 * M_];       // per-warp partials for K@c
    __shared__ float sh_r[M_];           // row scaling vector
    __shared__ float sh_scalar[8];       // final reduction

    // gt_local row norms: warps 0..4, one row each
    if (w < M_) {
        const float* g = gt_local + ((size_t)e * M_ + w) * D_;
        float s = 0.f;
        for (int d = lane; d < D_; d += 32) {
            float v = g[d];
            s += v * v;
        }
        #pragma unroll
        for (int off = 16; off > 0; off >>= 1)
            s += __shfl_down_sync(0xFFFFFFFFu, s, off);
        if (lane == 0) sh_gn[w] = sqrtf(s);
    }
    __syncthreads();

    // Build sim[m][n] and K[m][n] in registers
    const float fn = fmaxf(sqrtf(g_fnorm2[e][tid]), 1e-12f);
    float simv[M_], Kv[M_];
    #pragma unroll
    for (int m = 0; m < M_; m++) {
        const float gn = fmaxf(sh_gn[m], 1e-12f);
        simv[m] = g_dotmn[e][m][tid] / (gn * fn);
        Kv[m] = __expf((simv[m] - 1.0f) * 10.0f);   // exp(-(1-sim)/0.1)
    }

    // Sinkhorn loop (mirrors the reference exactly)
    const float u = 1.0f / (float)M_;
    const float vv = 1.0f / (float)N_;
    float c = 1.0f;
    float r[M_] = {1.f, 1.f, 1.f, 1.f, 1.f};
    float err = 1e9f;

    for (int it = 0; it < 100 && err >= 0.01f; ++it) {
        // Kc[m] = sum_n K[m][n] * c[n]
        float p[M_];
        #pragma unroll
        for (int m = 0; m < M_; m++) p[m] = Kv[m] * c;
        #pragma unroll
        for (int off = 16; off > 0; off >>= 1) {
            #pragma unroll
            for (int m = 0; m < M_; m++)
                p[m] += __shfl_down_sync(0xFFFFFFFFu, p[m], off);
        }
        if (lane == 0) {
            #pragma unroll
            for (int m = 0; m < M_; m++) sred[w * M_ + m] = p[m];
        }
        __syncthreads();
        if (tid < M_) {
            float s = 0.f;
            #pragma unroll
            for (int ww = 0; ww < 8; ww++) s += sred[ww * M_ + tid];
            sh_r[tid] = u / s;           // r = u / (K @ c)
        }
        __syncthreads();
        // all threads: identical update of r, err, c  (uniform branch)
        float errs = 0.f;
        #pragma unroll
        for (int m = 0; m < M_; m++) {
            float rn = sh_r[m];
            errs += fabsf(rn - r[m]);
            r[m] = rn;
        }
        err = errs * (1.0f / (float)M_);
        float ktr = 0.f;
        #pragma unroll
        for (int m = 0; m < M_; m++) ktr += Kv[m] * r[m];
        c = vv / ktr;                    // c = v / (K^T @ r)
    }

    // ot = sum_{m,n} r[m]*c[n]*K[m][n]*sim[m][n]
    float t = 0.f;
    #pragma unroll
    for (int m = 0; m < M_; m++) t += r[m] * Kv[m] * simv[m];
    t *= c;
    #pragma unroll
    for (int off = 16; off > 0; off >>= 1)
        t += __shfl_down_sync(0xFFFFFFFFu, t, off);
    if (lane == 0) sh_scalar[w] = t;
    __syncthreads();
    if (tid == 0) {
        float s = 0.f;
        #pragma unroll
        for (int ww = 0; ww < 8; ww++) s += sh_scalar[ww];
        g_ot[e] = s;
    }
}

// ---------------------------------------------------------------------------
// Kernel 3: finalize — deterministic sum of partials + scalar combine
// ---------------------------------------------------------------------------
__global__ void __launch_bounds__(TPB) k_final(float* __restrict__ out)
{
    const int tid = threadIdx.x;
    __shared__ float sh[TPB];
    float s = 0.f;
    for (int i = tid; i < NB_ALL; i += TPB) s += g_dot_partial[i];
    sh[tid] = s;
    __syncthreads();
    #pragma unroll
    for (int st = TPB / 2; st > 0; st >>= 1) {
        if (tid < st) sh[tid] += sh[tid + st];
        __syncthreads();
    }
    if (tid == 0) {
        float loss_global = sh[0] / (float)(E_ * B_);
        float loss_local = (g_ot[0] + g_ot[1] + g_ot[2]) * 2.0f / (float)E_;
        out[0] = loss_global + 0.1f * loss_local;
    }
}

// ---------------------------------------------------------------------------
extern "C" void kernel_launch(void* const* d_in, const int* in_sizes, int n_in,
                              void* d_out, int out_size)
{
    const float* feature        = (const float*)d_in[0];
    const float* gt             = (const float*)d_in[1];
    const float* gt_local       = (const float*)d_in[2];
    const float* feature_local  = (const float*)d_in[3];
    float* out = (float*)d_out;

    k_main<<<NB_ALL, TPB>>>(feature, gt, gt_local, feature_local);
    k_sinkhorn<<<E_, TPB>>>(gt_local);
    k_final<<<1, TPB>>>(out);
}

// round 10
// speedup vs baseline: 1.6470x; 1.2162x over previous
#include <cuda_runtime.h>
#include <cuda_bf16.h>
#include <math.h>

// Problem constants (fixed by the reference setup_inputs)
#define E_  3
#define B_  4096
#define D_  1024
#define M_  5
#define N_  256

#define NB_DOT 512          // blocks for the big feature*gt reduction
#define NB_SIM 96           // 3 e * 32 blocks, each block = 8 warps, 1 n per warp
#define TPB 256

// 24 float4-pairs per thread, unrolled by 4 -> 6 outer iterations, no tail.
#define STRIDE (NB_DOT * TPB)

// Scratch (allocation-free rule: __device__ globals)
__device__ float g_dot_partial[NB_DOT];
__device__ float g_dotmn[E_][M_][N_];   // raw dot(gt_local[m], feature_local[n])
__device__ float g_fnorm2[E_][N_];      // ||f_n||^2
__device__ float g_ot[E_];

static __device__ __forceinline__ float dot4(float4 a, float4 b) {
    return a.x * b.x + a.y * b.y + a.z * b.z + a.w * b.w;
}

// ---------------------------------------------------------------------------
// Kernel 1: (a) blocks [0, NB_DOT): grid-strided float4 dot of feature*gt,
//               front-batched 8 LDG.128 per iteration for MLP;
//           (b) blocks [NB_DOT, NB_DOT+NB_SIM): sim raw dots + f-row norms.
// ---------------------------------------------------------------------------
__global__ void __launch_bounds__(TPB, 4) k_main(
    const float* __restrict__ feature,
    const float* __restrict__ gt,
    const float* __restrict__ gt_local,
    const float* __restrict__ feature_local)
{
    const int b = blockIdx.x;
    const int tid = threadIdx.x;

    if (b < NB_DOT) {
        // ---- big streaming reduction: sum(feature * gt) ----
        const float4* fa = reinterpret_cast<const float4*>(feature);
        const float4* ga = reinterpret_cast<const float4*>(gt);
        int i = b * TPB + tid;
        float acc0 = 0.f, acc1 = 0.f, acc2 = 0.f, acc3 = 0.f;
        #pragma unroll 1
        for (int k = 0; k < 6; ++k) {
            // 8 independent 16B loads front-batched (read-once: evict-first)
            float4 x0 = __ldcs(&fa[i]);
            float4 x1 = __ldcs(&fa[i + STRIDE]);
            float4 x2 = __ldcs(&fa[i + 2 * STRIDE]);
            float4 x3 = __ldcs(&fa[i + 3 * STRIDE]);
            float4 y0 = __ldcs(&ga[i]);
            float4 y1 = __ldcs(&ga[i + STRIDE]);
            float4 y2 = __ldcs(&ga[i + 2 * STRIDE]);
            float4 y3 = __ldcs(&ga[i + 3 * STRIDE]);
            acc0 += dot4(x0, y0);
            acc1 += dot4(x1, y1);
            acc2 += dot4(x2, y2);
            acc3 += dot4(x3, y3);
            i += 4 * STRIDE;
        }
        float acc = (acc0 + acc1) + (acc2 + acc3);

        __shared__ float sh[TPB];
        sh[tid] = acc;
        __syncthreads();
        #pragma unroll
        for (int s = TPB / 2; s > 0; s >>= 1) {
            if (tid < s) sh[tid] += sh[tid + s];
            __syncthreads();
        }
        if (tid == 0) g_dot_partial[b] = sh[0];
    } else {
        // ---- sim raw dots + feature_local row norms ----
        const int sb = b - NB_DOT;          // 0..95
        const int e  = sb / 32;             // 3 extractors
        const int w  = tid >> 5;            // warp id 0..7
        const int lane = tid & 31;
        const int n  = (sb % 32) * 8 + w;   // 0..255

        const float* __restrict__ f = feature_local + ((size_t)e * N_ + n) * D_;
        const float* __restrict__ g = gt_local + (size_t)e * M_ * D_;

        float acc[M_] = {0.f, 0.f, 0.f, 0.f, 0.f};
        float fn = 0.f;
        for (int d = lane; d < D_; d += 32) {
            float fv = f[d];
            fn += fv * fv;
            #pragma unroll
            for (int m = 0; m < M_; m++)
                acc[m] += g[m * D_ + d] * fv;
        }
        #pragma unroll
        for (int off = 16; off > 0; off >>= 1) {
            fn += __shfl_down_sync(0xFFFFFFFFu, fn, off);
            #pragma unroll
            for (int m = 0; m < M_; m++)
                acc[m] += __shfl_down_sync(0xFFFFFFFFu, acc[m], off);
        }
        if (lane == 0) {
            #pragma unroll
            for (int m = 0; m < M_; m++)
                g_dotmn[e][m][n] = acc[m];
            g_fnorm2[e][n] = fn;
        }
    }
}

// ---------------------------------------------------------------------------
// Kernel 2: per-extractor Sinkhorn (one 256-thread block per e).
// Thread t owns column n = t of the 5 x 256 sim/K matrices (in registers).
// ---------------------------------------------------------------------------
__global__ void __launch_bounds__(TPB) k_sinkhorn(
    const float* __restrict__ gt_local)
{
    const int e = blockIdx.x;
    const int tid = threadIdx.x;         // == n
    const int w = tid >> 5;
    const int lane = tid & 31;

    __shared__ float sh_gn[M_];          // ||g_m||
    __shared__ float sred[8 * M_];       // per-warp partials for K@c
    __shared__ float sh_r[M_];           // row scaling vector
    __shared__ float sh_scalar[8];       // final reduction

    // gt_local row norms: warps 0..4, one row each
    if (w < M_) {
        const float* g = gt_local + ((size_t)e * M_ + w) * D_;
        float s = 0.f;
        for (int d = lane; d < D_; d += 32) {
            float v = g[d];
            s += v * v;
        }
        #pragma unroll
        for (int off = 16; off > 0; off >>= 1)
            s += __shfl_down_sync(0xFFFFFFFFu, s, off);
        if (lane == 0) sh_gn[w] = sqrtf(s);
    }
    __syncthreads();

    // Build sim[m][n] and K[m][n] in registers
    const float fn = fmaxf(sqrtf(g_fnorm2[e][tid]), 1e-12f);
    float simv[M_], Kv[M_];
    #pragma unroll
    for (int m = 0; m < M_; m++) {
        const float gn = fmaxf(sh_gn[m], 1e-12f);
        simv[m] = g_dotmn[e][m][tid] / (gn * fn);
        Kv[m] = __expf((simv[m] - 1.0f) * 10.0f);   // exp(-(1-sim)/0.1)
    }

    // Sinkhorn loop (mirrors the reference exactly)
    const float u = 1.0f / (float)M_;
    const float vv = 1.0f / (float)N_;
    float c = 1.0f;
    float r[M_] = {1.f, 1.f, 1.f, 1.f, 1.f};
    float err = 1e9f;

    for (int it = 0; it < 100 && err >= 0.01f; ++it) {
        // Kc[m] = sum_n K[m][n] * c[n]
        float p[M_];
        #pragma unroll
        for (int m = 0; m < M_; m++) p[m] = Kv[m] * c;
        #pragma unroll
        for (int off = 16; off > 0; off >>= 1) {
            #pragma unroll
            for (int m = 0; m < M_; m++)
                p[m] += __shfl_down_sync(0xFFFFFFFFu, p[m], off);
        }
        if (lane == 0) {
            #pragma unroll
            for (int m = 0; m < M_; m++) sred[w * M_ + m] = p[m];
        }
        __syncthreads();
        if (tid < M_) {
            float s = 0.f;
            #pragma unroll
            for (int ww = 0; ww < 8; ww++) s += sred[ww * M_ + tid];
            sh_r[tid] = u / s;           // r = u / (K @ c)
        }
        __syncthreads();
        // all threads: identical update of r, err, c  (uniform branch)
        float errs = 0.f;
        #pragma unroll
        for (int m = 0; m < M_; m++) {
            float rn = sh_r[m];
            errs += fabsf(rn - r[m]);
            r[m] = rn;
        }
        err = errs * (1.0f / (float)M_);
        float ktr = 0.f;
        #pragma unroll
        for (int m = 0; m < M_; m++) ktr += Kv[m] * r[m];
        c = vv / ktr;                    // c = v / (K^T @ r)
    }

    // ot = sum_{m,n} r[m]*c[n]*K[m][n]*sim[m][n]
    float t = 0.f;
    #pragma unroll
    for (int m = 0; m < M_; m++) t += r[m] * Kv[m] * simv[m];
    t *= c;
    #pragma unroll
    for (int off = 16; off > 0; off >>= 1)
        t += __shfl_down_sync(0xFFFFFFFFu, t, off);
    if (lane == 0) sh_scalar[w] = t;
    __syncthreads();
    if (tid == 0) {
        float s = 0.f;
        #pragma unroll
        for (int ww = 0; ww < 8; ww++) s += sh_scalar[ww];
        g_ot[e] = s;
    }
}

// ---------------------------------------------------------------------------
// Kernel 3: finalize — deterministic sum of partials + scalar combine
// ---------------------------------------------------------------------------
__global__ void __launch_bounds__(TPB) k_final(float* __restrict__ out)
{
    const int tid = threadIdx.x;
    __shared__ float sh[TPB];
    float s = 0.f;
    for (int i = tid; i < NB_DOT; i += TPB) s += g_dot_partial[i];
    sh[tid] = s;
    __syncthreads();
    #pragma unroll
    for (int st = TPB / 2; st > 0; st >>= 1) {
        if (tid < st) sh[tid] += sh[tid + st];
        __syncthreads();
    }
    if (tid == 0) {
        float loss_global = sh[0] / (float)(E_ * B_);
        float loss_local = (g_ot[0] + g_ot[1] + g_ot[2]) * 2.0f / (float)E_;
        out[0] = loss_global + 0.1f * loss_local;
    }
}

// ---------------------------------------------------------------------------
extern "C" void kernel_launch(void* const* d_in, const int* in_sizes, int n_in,
                              void* d_out, int out_size)
{
    const float* feature        = (const float*)d_in[0];
    const float* gt             = (const float*)d_in[1];
    const float* gt_local       = (const float*)d_in[2];
    const float* feature_local  = (const float*)d_in[3];
    float* out = (float*)d_out;

    k_main<<<NB_DOT + NB_SIM, TPB>>>(feature, gt, gt_local, feature_local);
    k_sinkhorn<<<E_, TPB>>>(gt_local);
    k_final<<<1, TPB>>>(out);
}